// round 3
// baseline (speedup 1.0000x reference)
#include <cuda_runtime.h>
#include <cuda_bf16.h>
#include <math.h>

#define B_SZ   16
#define C_IN   64
#define HH     256
#define WW     256
#define CKK    576
#define FC_DIM 512
#define IMG_PIX (HH * WW)
#define N_IMG  (B_SZ * C_IN)
#define FOUT_ELEMS ((size_t)N_IMG * IMG_PIX)

__device__ float g_kw[B_SZ * CKK];   // softmaxed kernel weights

// ---------------------------------------------------------------------------
// Fused MLP: relu(Fc@W1+b1) @ W2 + b2 -> softmax.  One block per batch sample.
// 576 threads. Deep unroll + 4 accumulators to hide DRAM latency.
// ---------------------------------------------------------------------------
__global__ __launch_bounds__(CKK) void EKG_mlp_fused(
    const float* __restrict__ Fc,
    const float* __restrict__ W1, const float* __restrict__ b1,
    const float* __restrict__ W2, const float* __restrict__ b2,
    float* __restrict__ kw_tail, int write_tail)
{
    __shared__ float sin_[FC_DIM];
    __shared__ float sh_h[CKK];
    __shared__ float red[32];
    __shared__ float bcast;

    const int b = blockIdx.x;
    const int j = threadIdx.x;
    const int lane = j & 31;
    const int wid  = j >> 5;

    if (j < FC_DIM) sin_[j] = Fc[b * FC_DIM + j];
    __syncthreads();

    // ---- Layer 1: 512 -> 576, 4 independent chains, 32 loads in flight ----
    {
        float a0 = 0.f, a1 = 0.f, a2 = 0.f, a3 = 0.f;
        const float* __restrict__ wp = W1 + j;
        #pragma unroll 8
        for (int i = 0; i < FC_DIM; i += 4) {
            a0 = fmaf(sin_[i + 0], wp[(i + 0) * CKK], a0);
            a1 = fmaf(sin_[i + 1], wp[(i + 1) * CKK], a1);
            a2 = fmaf(sin_[i + 2], wp[(i + 2) * CKK], a2);
            a3 = fmaf(sin_[i + 3], wp[(i + 3) * CKK], a3);
        }
        sh_h[j] = fmaxf(b1[j] + ((a0 + a1) + (a2 + a3)), 0.0f);
    }
    __syncthreads();

    // ---- Layer 2: 576 -> 576 ----
    float logit;
    {
        float a0 = 0.f, a1 = 0.f, a2 = 0.f, a3 = 0.f;
        const float* __restrict__ wp = W2 + j;
        #pragma unroll 8
        for (int i = 0; i < CKK; i += 4) {
            a0 = fmaf(sh_h[i + 0], wp[(i + 0) * CKK], a0);
            a1 = fmaf(sh_h[i + 1], wp[(i + 1) * CKK], a1);
            a2 = fmaf(sh_h[i + 2], wp[(i + 2) * CKK], a2);
            a3 = fmaf(sh_h[i + 3], wp[(i + 3) * CKK], a3);
        }
        logit = b2[j] + ((a0 + a1) + (a2 + a3));
    }

    // ---- Softmax over 576 ----
    float m = logit;
    #pragma unroll
    for (int o = 16; o > 0; o >>= 1)
        m = fmaxf(m, __shfl_xor_sync(0xffffffffu, m, o));
    if (lane == 0) red[wid] = m;
    __syncthreads();
    if (wid == 0) {
        float v = (lane < 18) ? red[lane] : -INFINITY;
        #pragma unroll
        for (int o = 16; o > 0; o >>= 1)
            v = fmaxf(v, __shfl_xor_sync(0xffffffffu, v, o));
        if (lane == 0) bcast = v;
    }
    __syncthreads();
    const float e = expf(logit - bcast);

    float s = e;
    #pragma unroll
    for (int o = 16; o > 0; o >>= 1)
        s += __shfl_xor_sync(0xffffffffu, s, o);
    __syncthreads();
    if (lane == 0) red[wid] = s;
    __syncthreads();
    if (wid == 0) {
        float v = (lane < 18) ? red[lane] : 0.0f;
        #pragma unroll
        for (int o = 16; o > 0; o >>= 1)
            v += __shfl_xor_sync(0xffffffffu, v, o);
        if (lane == 0) bcast = v;
    }
    __syncthreads();

    const float kw = e / bcast;
    g_kw[b * CKK + j] = kw;
    if (write_tail) kw_tail[b * CKK + j] = kw;
}

// ---------------------------------------------------------------------------
// Depthwise 3x3 conv, reflect pad, NO shared memory.
// Each thread owns 4 cols (float4) and 8 rows; window rows loaded directly
// from global (neighbor scalars are L1 hits on lines the warp just fetched).
// Block 256: tx=0..63 (col group), ty=0..3 (row strip). Block tile: 256x32.
// Grid (8, 1024).
// ---------------------------------------------------------------------------
#define ROWS_PER_BLOCK 32
#define ROWS_PER_THREAD 8

__device__ __forceinline__ void load_row6(
    const float* __restrict__ img, int gr, int tx, float* __restrict__ w)
{
    gr = (gr < 0) ? 1 : ((gr > HH - 1) ? (2 * HH - 2 - gr) : gr);
    const float* rowp = img + gr * WW;
    const float4 q = __ldg((const float4*)rowp + tx);
    w[1] = q.x; w[2] = q.y; w[3] = q.z; w[4] = q.w;
    w[0] = (tx == 0)      ? q.y : __ldg(rowp + 4 * tx - 1);
    w[5] = (tx == WW/4-1) ? q.z : __ldg(rowp + 4 * tx + 4);
}

__global__ __launch_bounds__(256) void EKG_conv_kernel(
    const float* __restrict__ Fd,
    float* __restrict__ out)
{
    const int bc   = blockIdx.y;
    const int tid  = threadIdx.x;
    const int tx   = tid & 63;
    const int ty   = tid >> 6;
    const int rbase = blockIdx.x * ROWS_PER_BLOCK + ty * ROWS_PER_THREAD;

    const float* __restrict__ img = Fd  + (size_t)bc * IMG_PIX;
    float*       __restrict__ o   = out + (size_t)bc * IMG_PIX;

    const float* kwp = g_kw + bc * 9;
    const float w00 = __ldg(kwp+0), w01 = __ldg(kwp+1), w02 = __ldg(kwp+2);
    const float w10 = __ldg(kwp+3), w11 = __ldg(kwp+4), w12 = __ldg(kwp+5);
    const float w20 = __ldg(kwp+6), w21 = __ldg(kwp+7), w22 = __ldg(kwp+8);

    float win[3][6];
    load_row6(img, rbase - 1, tx, win[0]);
    load_row6(img, rbase + 0, tx, win[1]);

    #pragma unroll
    for (int rr = 0; rr < ROWS_PER_THREAD; ++rr) {
        load_row6(img, rbase + rr + 1, tx, win[(rr + 2) % 3]);

        const float* T  = win[rr % 3];
        const float* M  = win[(rr + 1) % 3];
        const float* Bt = win[(rr + 2) % 3];

        float4 r;
        r.x = w00*T[0]; r.x = fmaf(w01,T[1],r.x); r.x = fmaf(w02,T[2],r.x);
        r.x = fmaf(w10,M[0],r.x); r.x = fmaf(w11,M[1],r.x); r.x = fmaf(w12,M[2],r.x);
        r.x = fmaf(w20,Bt[0],r.x); r.x = fmaf(w21,Bt[1],r.x); r.x = fmaf(w22,Bt[2],r.x);

        r.y = w00*T[1]; r.y = fmaf(w01,T[2],r.y); r.y = fmaf(w02,T[3],r.y);
        r.y = fmaf(w10,M[1],r.y); r.y = fmaf(w11,M[2],r.y); r.y = fmaf(w12,M[3],r.y);
        r.y = fmaf(w20,Bt[1],r.y); r.y = fmaf(w21,Bt[2],r.y); r.y = fmaf(w22,Bt[3],r.y);

        r.z = w00*T[2]; r.z = fmaf(w01,T[3],r.z); r.z = fmaf(w02,T[4],r.z);
        r.z = fmaf(w10,M[2],r.z); r.z = fmaf(w11,M[3],r.z); r.z = fmaf(w12,M[4],r.z);
        r.z = fmaf(w20,Bt[2],r.z); r.z = fmaf(w21,Bt[3],r.z); r.z = fmaf(w22,Bt[4],r.z);

        r.w = w00*T[3]; r.w = fmaf(w01,T[4],r.w); r.w = fmaf(w02,T[5],r.w);
        r.w = fmaf(w10,M[3],r.w); r.w = fmaf(w11,M[4],r.w); r.w = fmaf(w12,M[5],r.w);
        r.w = fmaf(w20,Bt[3],r.w); r.w = fmaf(w21,Bt[4],r.w); r.w = fmaf(w22,Bt[5],r.w);

        __stcs((float4*)(o + (size_t)(rbase + rr) * WW + 4 * tx), r);
    }
}

// ---------------------------------------------------------------------------
extern "C" void kernel_launch(void* const* d_in, const int* in_sizes, int n_in,
                              void* d_out, int out_size) {
    const float* Fd = (const float*)d_in[0];
    const float* Fc = (const float*)d_in[1];
    const float* W1 = (const float*)d_in[2];
    const float* b1 = (const float*)d_in[3];
    const float* W2 = (const float*)d_in[4];
    const float* b2 = (const float*)d_in[5];
    float* out = (float*)d_out;

    const int write_tail = ((size_t)out_size >= FOUT_ELEMS + (size_t)B_SZ * CKK) ? 1 : 0;
    float* kw_tail = out + FOUT_ELEMS;

    EKG_mlp_fused<<<B_SZ, CKK>>>(Fc, W1, b1, W2, b2, kw_tail, write_tail);

    dim3 grid(HH / ROWS_PER_BLOCK, N_IMG);
    EKG_conv_kernel<<<grid, 256>>>(Fd, out);
}